// round 4
// baseline (speedup 1.0000x reference)
#include <cuda_runtime.h>

// GEMV: out[1, 8192] = x[1, 8192] @ W[8192, 8192] + b
// Inputs (metadata order): d_in[0]=x (8192 f32), d_in[1]=W (8192*8192 f32,
// row-major [IN_LEN, OUT_LEN]), d_in[2]=b (8192 f32). Output: 8192 f32.
//
// Strategy: HBM-bound (256 MB of W read once). Row-major W means we
// parallelize over OUTPUT columns (coalesced float4 loads across threads)
// and loop over input rows, with split-K across blocks via atomicAdd.
// Bias is pre-seeded into out by a tiny init kernel.

static constexpr int IN_LEN  = 8192;
static constexpr int OUT_LEN = 8192;

static constexpr int THREADS        = 128;
static constexpr int COLS_PER_BLOCK = THREADS * 4;          // 512 cols (float4/thread)
static constexpr int COL_BLOCKS     = OUT_LEN / COLS_PER_BLOCK;  // 16
static constexpr int ROWS_PER_SPLIT = 128;
static constexpr int ROW_SPLITS     = IN_LEN / ROWS_PER_SPLIT;   // 64
// grid = 16 x 64 = 1024 blocks -> ~7 CTAs/SM on 148/152 SMs.

__global__ void dense_init_bias(const float* __restrict__ b,
                                float* __restrict__ out) {
    int j = blockIdx.x * blockDim.x + threadIdx.x;
    if (j < OUT_LEN) out[j] = b[j];
}

__global__ __launch_bounds__(THREADS)
void dense_gemv_splitk(const float* __restrict__ x,
                       const float* __restrict__ W,
                       float* __restrict__ out) {
    const int col0 = blockIdx.x * COLS_PER_BLOCK + threadIdx.x * 4;
    const int row0 = blockIdx.y * ROWS_PER_SPLIT;

    __shared__ float xs[ROWS_PER_SPLIT];
    if (threadIdx.x < ROWS_PER_SPLIT) xs[threadIdx.x] = x[row0 + threadIdx.x];
    __syncthreads();

    const float4* __restrict__ Wp =
        reinterpret_cast<const float4*>(W + (size_t)row0 * OUT_LEN + col0);
    const size_t row_stride_v4 = OUT_LEN / 4;

    float4 acc = make_float4(0.f, 0.f, 0.f, 0.f);

    // Unroll 8 -> 8 independent float4 LDGs in flight per thread (MLP to
    // hide ~577-cycle DRAM latency). Accumulator chain is 4 independent
    // FMA streams; FMA pipe is ~10x away from being the bottleneck.
    #pragma unroll 8
    for (int i = 0; i < ROWS_PER_SPLIT; i++) {
        const float xv = xs[i];
        const float4 w = Wp[(size_t)i * row_stride_v4];
        acc.x = fmaf(xv, w.x, acc.x);
        acc.y = fmaf(xv, w.y, acc.y);
        acc.z = fmaf(xv, w.z, acc.z);
        acc.w = fmaf(xv, w.w, acc.w);
    }

    // Split-K combine: 64 atomic adds per output over the kernel lifetime,
    // spread across 8192 addresses -> fully hidden under the HBM stream.
    atomicAdd(&out[col0 + 0], acc.x);
    atomicAdd(&out[col0 + 1], acc.y);
    atomicAdd(&out[col0 + 2], acc.z);
    atomicAdd(&out[col0 + 3], acc.w);
}

extern "C" void kernel_launch(void* const* d_in, const int* in_sizes, int n_in,
                              void* d_out, int out_size) {
    const float* x = (const float*)d_in[0];
    const float* W = (const float*)d_in[1];
    const float* b = (const float*)d_in[2];
    float* out = (float*)d_out;

    dense_init_bias<<<OUT_LEN / 256, 256>>>(b, out);

    dim3 grid(COL_BLOCKS, ROW_SPLITS);
    dense_gemv_splitk<<<grid, THREADS>>>(x, W, out);
}